// round 8
// baseline (speedup 1.0000x reference)
#include <cuda_runtime.h>
#include <cuda_fp16.h>

// Problem constants
#define B_DIM 8
#define C_DIM 64
#define T_DIM 128
#define N_DIM 207
#define TN    (T_DIM * N_DIM)   // 26496 pixels per (b, channel)
#define JT_BLK 96               // proj: pixels per block tile (26496 = 96*276)
#define NBLK_J (TN / JT_BLK)    // 276
#define L2E   1.4426950408889634f

// fp16 scratch for projected Q (pre-scaled by log2e), K, V.
__device__ __align__(16) unsigned short g_scr[3][(size_t)B_DIM * C_DIM * TN];

// ---------------- helpers ----------------
// Swizzled half-index into the transposed X tile Xs[j][c] (see R3 notes):
// conflict-free for transposed 16-bit stores and m16n8k16 A-fragment loads.
__device__ __forceinline__ int xs_idx(int j, int c) {
    return j * 72 + (c ^ (((j >> 3) & 3) << 1));
}

__device__ __forceinline__ void mma_fp16(float* d, const unsigned* a, const unsigned* b) {
    asm volatile(
        "mma.sync.aligned.m16n8k16.row.col.f32.f16.f16.f32 "
        "{%0,%1,%2,%3},{%4,%5,%6,%7},{%8,%9},{%0,%1,%2,%3};\n"
        : "+f"(d[0]), "+f"(d[1]), "+f"(d[2]), "+f"(d[3])
        : "r"(a[0]), "r"(a[1]), "r"(a[2]), "r"(a[3]),
          "r"(b[0]), "r"(b[1]));
}

// Guaranteed single-MUFU exp2 (independent of fast-math flags)
__device__ __forceinline__ float ex2f(float x) {
    float y;
    asm("ex2.approx.f32 %0, %1;" : "=f"(y) : "f"(x));
    return y;
}

// ---------------- Kernel A: projections via fp16 tensor cores (single pass) ----------------
// grid = (276 j-tiles, 8 batches, 3 projections), 192 threads (6 warps).
// Y[96 j][64 o] = X[64 c][96 j]^T * W[64 o][64 c]^T + bias, fp32 accum.
#define YS_STRIDE 100   // fp32 words; conflict-free for fragment writes
__global__ __launch_bounds__(192) void proj_kernel(
    const float* __restrict__ q, const float* __restrict__ k, const float* __restrict__ v,
    const float* __restrict__ Wq, const float* __restrict__ bq,
    const float* __restrict__ Wk, const float* __restrict__ bk,
    const float* __restrict__ Wv, const float* __restrict__ bv)
{
    // Union: Xh (staging + MMA A operand, 13824 B) shares bytes with Ysm (25600 B)
    __shared__ __align__(16) char smem_u[64 * YS_STRIDE * sizeof(float)];
    __shared__ unsigned short Wh[64 * 72];
    __shared__ float bias_s[64];

    unsigned short* Xh = (unsigned short*)smem_u;
    float* Ysm = (float*)smem_u;

    const int z = blockIdx.z;
    const float* __restrict__ X = (z == 0) ? q : (z == 1) ? k : v;
    const float* __restrict__ W = (z == 0) ? Wq : (z == 1) ? Wk : Wv;
    const float* __restrict__ bb = (z == 0) ? bq : (z == 1) ? bk : bv;
    __half* __restrict__ O = (__half*)g_scr[z];

    const int b   = blockIdx.y;
    const int j0  = blockIdx.x * JT_BLK;
    const int tid = threadIdx.x;

    // Weights -> fp16 SMEM (stride 72: B-fragment reads conflict-free)
    for (int idx = tid; idx < 64 * 64; idx += 192) {
        int o = idx >> 6, c = idx & 63;
        __half h = __float2half_rn(W[idx]);
        Wh[o * 72 + c] = *(unsigned short*)&h;
    }
    if (tid < 64) bias_s[tid] = bb[tid];

    // X tile [64 c][96 j] -> transposed fp16 Xs[j][c]
    {
        const int jl  = tid % JT_BLK;       // 0..95
        const int cst = tid / JT_BLK;       // 0 or 1
        const float* Xb = X + ((size_t)b * C_DIM) * TN + j0 + jl;
        #pragma unroll
        for (int c = 0; c < 64; c += 2) {
            int cc = c + cst;
            float x = Xb[(size_t)cc * TN];
            __half h = __float2half_rn(x);
            Xh[xs_idx(jl, cc)] = *(unsigned short*)&h;
        }
    }
    __syncthreads();

    // Warp tiling: 6 warps = 3 (j) x 2 (o); warp tile 32j x 32o
    const int wid = tid >> 5, lane = tid & 31;
    const int wj = wid % 3, wo = wid / 3;
    const int lr = lane >> 2, lc = lane & 3;

    const unsigned* Xh32 = (const unsigned*)Xh;
    const unsigned* Wh32 = (const unsigned*)Wh;

    float acc[2][4][4] = {};

    #pragma unroll
    for (int k0 = 0; k0 < 64; k0 += 16) {
        unsigned Ah[2][4];
        #pragma unroll
        for (int mt = 0; mt < 2; mt++) {
            int jb = wj * 32 + mt * 16;
            int r0 = jb + lr, r1 = jb + lr + 8;
            int c0 = k0 + 2 * lc, c1 = k0 + 2 * lc + 8;
            Ah[mt][0] = Xh32[xs_idx(r0, c0) >> 1];
            Ah[mt][1] = Xh32[xs_idx(r1, c0) >> 1];
            Ah[mt][2] = Xh32[xs_idx(r0, c1) >> 1];
            Ah[mt][3] = Xh32[xs_idx(r1, c1) >> 1];
        }
        unsigned Bh[4][2];
        #pragma unroll
        for (int nt = 0; nt < 4; nt++) {
            int o = wo * 32 + nt * 8 + lr;
            int c0 = k0 + 2 * lc;
            Bh[nt][0] = Wh32[(o * 72 + c0) >> 1];
            Bh[nt][1] = Wh32[(o * 72 + c0 + 8) >> 1];
        }
        #pragma unroll
        for (int mt = 0; mt < 2; mt++) {
            #pragma unroll
            for (int nt = 0; nt < 4; nt++) {
                mma_fp16(acc[mt][nt], Ah[mt], Bh[nt]);
            }
        }
    }

    // Epilogue: acc -> Ysm (f32, conflict-free) -> pack half2 -> coalesced STG.64
    __syncthreads();   // done reading Xh; safe to overwrite with Ysm
    const float qs = (z == 0) ? L2E : 1.0f;
    #pragma unroll
    for (int mt = 0; mt < 2; mt++) {
        #pragma unroll
        for (int nt = 0; nt < 4; nt++) {
            int jb = wj * 32 + mt * 16;
            int ob = wo * 32 + nt * 8 + 2 * lc;
            int r0 = jb + lr, r1 = r0 + 8;
            float b0 = bias_s[ob], b1 = bias_s[ob + 1];
            Ysm[ob * YS_STRIDE + r0]       = (acc[mt][nt][0] + b0) * qs;
            Ysm[(ob + 1) * YS_STRIDE + r0] = (acc[mt][nt][1] + b1) * qs;
            Ysm[ob * YS_STRIDE + r1]       = (acc[mt][nt][2] + b0) * qs;
            Ysm[(ob + 1) * YS_STRIDE + r1] = (acc[mt][nt][3] + b1) * qs;
        }
    }
    __syncthreads();

    {
        const size_t obase = ((size_t)b * C_DIM) * TN + j0;   // half index
        if (lane < 24) {
            #pragma unroll
            for (int o = wid; o < 64; o += 6) {   // 6 warps cover 64 rows
                float4 val = *(const float4*)&Ysm[o * YS_STRIDE + 4 * lane];
                __half2 h01 = __floats2half2_rn(val.x, val.y);
                __half2 h23 = __floats2half2_rn(val.z, val.w);
                uint2 pk;
                pk.x = *(unsigned*)&h01;
                pk.y = *(unsigned*)&h23;
                *(uint2*)&O[obase + (size_t)o * TN + 4 * lane] = pk;   // 8B aligned
            }
        }
    }
}

// ---------------- Kernel B: 7-tap sliding-window softmax, register window ----------------
// grid = (4 t-chunks of 32, 64 channels, 8 batches), 224 threads (lane = n).
// Fully unrolled (window shift = register renaming). Head/tail guards only in
// the blocks that need them. No max-sub: |score*log2e| << 126, exp2 safe;
// zero-pad taps give exp(0)=1 matching the reference softmax exactly.
#define TTC 32

template<bool HG, bool TG>
__device__ __forceinline__ void attn_chunk(
    const __half* __restrict__ Q, const __half* __restrict__ K,
    const __half* __restrict__ V, float* __restrict__ out,
    unsigned base, int t0, int n)
{
    float kw[7], vw[7];
    #pragma unroll
    for (int i = 0; i < 6; i++) {              // slots for t = t0-3 .. t0+2
        int t = t0 - 3 + i;
        bool ok = !HG || (t >= 0);
        unsigned g = base + (unsigned)(ok ? t : 0) * N_DIM + n;
        kw[i] = ok ? __half2float(K[g]) : 0.0f;
        vw[i] = ok ? __half2float(V[g]) : 0.0f;
    }

    unsigned gi = base + (unsigned)t0 * N_DIM + n;   // index of (t, n)
    #pragma unroll
    for (int tl = 0; tl < TTC; tl++) {
        bool ok = !TG || (t0 + tl + 3 < T_DIM);
        unsigned gl = gi + 3 * N_DIM;
        kw[6] = ok ? __half2float(K[gl]) : 0.0f;
        vw[6] = ok ? __half2float(V[gl]) : 0.0f;

        float qv = __half2float(Q[gi]);        // already log2e-scaled

        float den = 0.0f, num = 0.0f;
        #pragma unroll
        for (int i = 0; i < 7; i++) {
            float e = ex2f(qv * kw[i]);
            den += e;
            num = fmaf(e, vw[i], num);
        }
        out[gi] = __fdividef(num, den);

        #pragma unroll
        for (int i = 0; i < 6; i++) { kw[i] = kw[i + 1]; vw[i] = vw[i + 1]; }
        gi += N_DIM;
    }
}

__global__ __launch_bounds__(224) void attn_kernel(float* __restrict__ out)
{
    const int n = threadIdx.x;
    if (n >= N_DIM) return;

    const int t0 = blockIdx.x * TTC;
    const unsigned base = ((unsigned)blockIdx.z * C_DIM + blockIdx.y) * TN;

    const __half* __restrict__ Q = (const __half*)g_scr[0];
    const __half* __restrict__ K = (const __half*)g_scr[1];
    const __half* __restrict__ V = (const __half*)g_scr[2];

    if (blockIdx.x == 0)
        attn_chunk<true, false>(Q, K, V, out, base, t0, n);   // head guard
    else if (blockIdx.x == (T_DIM / TTC) - 1)
        attn_chunk<false, true>(Q, K, V, out, base, t0, n);   // tail guard
    else
        attn_chunk<false, false>(Q, K, V, out, base, t0, n);  // branch-free
}

// ---------------- launch ----------------
extern "C" void kernel_launch(void* const* d_in, const int* in_sizes, int n_in,
                              void* d_out, int out_size)
{
    (void)in_sizes; (void)n_in; (void)out_size;
    const float* q  = (const float*)d_in[0];
    const float* k  = (const float*)d_in[1];
    const float* v  = (const float*)d_in[2];
    const float* Wq = (const float*)d_in[3];
    const float* bq = (const float*)d_in[4];
    const float* Wk = (const float*)d_in[5];
    const float* bk = (const float*)d_in[6];
    const float* Wv = (const float*)d_in[7];
    const float* bv = (const float*)d_in[8];

    dim3 gA(NBLK_J, B_DIM, 3);
    proj_kernel<<<gA, 192>>>(q, k, v, Wq, bq, Wk, bk, Wv, bv);

    dim3 gB(T_DIM / TTC, C_DIM, B_DIM);
    attn_kernel<<<gB, 224>>>((float*)d_out);
}